// round 9
// baseline (speedup 1.0000x reference)
#include <cuda_runtime.h>

// out[b,i,j,f] = x[b,i,f] * y[b,j,f]; d_out second half = 0.75 * first half.
// ONE store per thread over the ENTIRE output (both halves): thread idx
// writes out[idx], scale chosen by half -> the global write stream is a
// single perfectly linear sweep (no interleaving of two streams 461MB apart).
// Loads are re-read 6x across threads but hit L1/L2 (plenty of headroom);
// DRAM read traffic stays at the mandatory minimum.

__global__ __launch_bounds__(256)
void tp_kernel(const float4* __restrict__ x,
               const float4* __restrict__ y,
               float4* __restrict__ out,
               unsigned total2, unsigned halfi)
{
    unsigned idx = blockIdx.x * blockDim.x + threadIdx.x;
    if (idx >= total2) return;

    unsigned e = idx;
    float scale = 1.0f;
    if (e >= halfi) { e -= halfi; scale = 0.75f; }

    unsigned f4 = e & 31u;
    unsigned g  = e >> 5;            // b*9 + ij
    unsigned b  = g / 9u;
    unsigned ij = g - b * 9u;
    unsigned i  = ij / 3u;
    unsigned j  = ij - i * 3u;

    float4 xv = x[(b * 3u + i) * 32u + f4];
    float4 yv = y[(b * 3u + j) * 32u + f4];

    float4 p;
    p.x = scale * (xv.x * yv.x);
    p.y = scale * (xv.y * yv.y);
    p.z = scale * (xv.z * yv.z);
    p.w = scale * (xv.w * yv.w);

    out[idx] = p;
}

extern "C" void kernel_launch(void* const* d_in, const int* in_sizes, int n_in,
                              void* d_out, int out_size)
{
    const float4* x = (const float4*)d_in[0];
    const float4* y = (const float4*)d_in[1];
    float4* out = (float4*)d_out;

    int B = in_sizes[0] / (3 * 128);          // 100000
    unsigned halfi  = (unsigned)B * 9u * 32u; // float4 elems in first half
    unsigned total2 = halfi * 2u;             // both halves
    int threads = 256;
    int blocks = (int)((total2 + threads - 1) / threads);
    tp_kernel<<<blocks, threads>>>(x, y, out, total2, halfi);
}

// round 10
// speedup vs baseline: 1.3880x; 1.3880x over previous
#include <cuda_runtime.h>

// out[b,i,j,f] = x[b,i,f] * y[b,j,f]; d_out second half = 0.75 * first half.
// One thread per (b, i, f4): loads x[b,i] once + y[b,0..2] (4 loads),
// computes 3 j-products, stores 3+3 float4 (both halves). Per 3 output
// units: 4 loads + 6 stores (vs 6+6 in the one-store-pair-per-thread shape).
// Stores per thread span 3 consecutive ij rows -> locally linear write
// stream; temporal locality of y reuse stays within a block's lifetime.

__global__ __launch_bounds__(256)
void tp_kernel(const float4* __restrict__ x,
               const float4* __restrict__ y,
               float4* __restrict__ out,
               unsigned total, unsigned halfi)
{
    unsigned idx = blockIdx.x * blockDim.x + threadIdx.x;
    if (idx >= total) return;

    unsigned f4 = idx & 31u;
    unsigned g  = idx >> 5;          // b*3 + i
    unsigned b  = g / 3u;
    unsigned i  = g - b * 3u;

    float4 xv = x[g * 32u + f4];

    float4 yv[3];
#pragma unroll
    for (int j = 0; j < 3; j++)
        yv[j] = y[(b * 3u + j) * 32u + f4];

    // output base for (b, i, j=0)
    unsigned obase = (b * 9u + i * 3u) * 32u + f4;

#pragma unroll
    for (int j = 0; j < 3; j++) {
        float4 p;
        p.x = xv.x * yv[j].x;
        p.y = xv.y * yv[j].y;
        p.z = xv.z * yv[j].z;
        p.w = xv.w * yv[j].w;
        out[obase + j * 32u] = p;

        float4 q;
        q.x = 0.75f * p.x;
        q.y = 0.75f * p.y;
        q.z = 0.75f * p.z;
        q.w = 0.75f * p.w;
        out[halfi + obase + j * 32u] = q;
    }
}

extern "C" void kernel_launch(void* const* d_in, const int* in_sizes, int n_in,
                              void* d_out, int out_size)
{
    const float4* x = (const float4*)d_in[0];
    const float4* y = (const float4*)d_in[1];
    float4* out = (float4*)d_out;

    int B = in_sizes[0] / (3 * 128);          // 100000
    unsigned total = (unsigned)B * 3u * 32u;  // threads: (b, i, f4)
    unsigned halfi = (unsigned)B * 9u * 32u;  // float4 elems in first half
    int threads = 256;
    int blocks = (int)((total + threads - 1) / threads);
    tp_kernel<<<blocks, threads>>>(x, y, out, total, halfi);
}

// round 11
// speedup vs baseline: 1.3902x; 1.0016x over previous
#include <cuda_runtime.h>

// out[b,i,j,f] = x[b,i,f] * y[b,j,f]; d_out second half = 0.75 * first half.
// One thread per (b, i, f4): 4 loads (x[b,i], y[b,0..2]), 6 stores.
// Stores GROUPED BY HALF: 3 consecutive ij-rows in half A, then 3 in half B
// (vs alternating between halves 461MB apart on every other store).
// 128-thread blocks: finest-grain HW work distribution (best regime R6/R10).

__global__ __launch_bounds__(128)
void tp_kernel(const float4* __restrict__ x,
               const float4* __restrict__ y,
               float4* __restrict__ out,
               unsigned total, unsigned halfi)
{
    unsigned idx = blockIdx.x * blockDim.x + threadIdx.x;
    if (idx >= total) return;

    unsigned f4 = idx & 31u;
    unsigned g  = idx >> 5;          // b*3 + i
    unsigned b  = g / 3u;
    unsigned i  = g - b * 3u;

    float4 xv = x[g * 32u + f4];

    float4 yv[3];
#pragma unroll
    for (int j = 0; j < 3; j++)
        yv[j] = y[(b * 3u + j) * 32u + f4];

    float4 p[3];
#pragma unroll
    for (int j = 0; j < 3; j++) {
        p[j].x = xv.x * yv[j].x;
        p[j].y = xv.y * yv[j].y;
        p[j].z = xv.z * yv[j].z;
        p[j].w = xv.w * yv[j].w;
    }

    unsigned obase = (b * 9u + i * 3u) * 32u + f4;

#pragma unroll
    for (int j = 0; j < 3; j++)
        out[obase + j * 32u] = p[j];

#pragma unroll
    for (int j = 0; j < 3; j++) {
        float4 q;
        q.x = 0.75f * p[j].x;
        q.y = 0.75f * p[j].y;
        q.z = 0.75f * p[j].z;
        q.w = 0.75f * p[j].w;
        out[halfi + obase + j * 32u] = q;
    }
}

extern "C" void kernel_launch(void* const* d_in, const int* in_sizes, int n_in,
                              void* d_out, int out_size)
{
    const float4* x = (const float4*)d_in[0];
    const float4* y = (const float4*)d_in[1];
    float4* out = (float4*)d_out;

    int B = in_sizes[0] / (3 * 128);          // 100000
    unsigned total = (unsigned)B * 3u * 32u;  // threads: (b, i, f4)
    unsigned halfi = (unsigned)B * 9u * 32u;  // float4 elems in first half
    int threads = 128;
    int blocks = (int)((total + threads - 1) / threads);
    tp_kernel<<<blocks, threads>>>(x, y, out, total, halfi);
}